// round 10
// baseline (speedup 1.0000x reference)
#include <cuda_runtime.h>
#include <cuda_bf16.h>
#include <cstdint>
#include <math.h>

#define SS 2048
#define DM 1024
#define DH 4096
#define MM 8192

// ---------------- device scratch ----------------
__device__ double g_partial[8192];
__device__ float  g_wscale[4];
__device__ __align__(16) int8_t g_xq [(size_t)MM * DM];
__device__ __align__(16) int8_t g_wq1[(size_t)DH * DM];
__device__ __align__(16) int8_t g_wq2[(size_t)DM * DH];
__device__ __align__(16) int8_t g_q2 [(size_t)MM * DH];
__device__ __align__(16) float  g_h  [(size_t)MM * DH];
__device__ float g_rowscale1[MM];
__device__ float g_rowscale2[MM];

// ---------------- helpers ----------------
__device__ __forceinline__ float block_max(float v, float* sred, int tid, int nthr) {
    #pragma unroll
    for (int o = 16; o > 0; o >>= 1) v = fmaxf(v, __shfl_xor_sync(0xFFFFFFFFu, v, o));
    if ((tid & 31) == 0) sred[tid >> 5] = v;
    __syncthreads();
    int nw = nthr >> 5;
    if (tid < 32) {
        float x = (tid < nw) ? sred[tid] : 0.0f;
        #pragma unroll
        for (int o = 16; o > 0; o >>= 1) x = fmaxf(x, __shfl_xor_sync(0xFFFFFFFFu, x, o));
        if (tid == 0) sred[0] = x;
    }
    __syncthreads();
    float r = sred[0];
    __syncthreads();
    return r;
}
__device__ __forceinline__ int q8(float v, float s, float lo, float hi) {
    return (int)fminf(fmaxf(rintf(v * s), lo), hi);
}

// ---------------- weight mean|w| (deterministic) ----------------
__global__ void wsum_partial(const float* __restrict__ w1, const float* __restrict__ w2) {
    __shared__ double sd[256];
    int blk = blockIdx.x;
    const float* src = (blk < 4096) ? (w1 + (size_t)blk * 1024)
                                    : (w2 + (size_t)(blk - 4096) * 1024);
    int tid = threadIdx.x;
    float4 v = reinterpret_cast<const float4*>(src)[tid];
    double s = ((double)fabsf(v.x) + (double)fabsf(v.y)) +
               ((double)fabsf(v.z) + (double)fabsf(v.w));
    sd[tid] = s; __syncthreads();
    for (int o = 128; o > 0; o >>= 1) { if (tid < o) sd[tid] += sd[tid + o]; __syncthreads(); }
    if (tid == 0) g_partial[blk] = sd[0];
}

__global__ void wsum_final() {
    __shared__ double sd[256];
    int tid = threadIdx.x;
    for (int a = 0; a < 2; a++) {
        double s = 0.0;
        for (int i = tid; i < 4096; i += 256) s += g_partial[a * 4096 + i];
        sd[tid] = s; __syncthreads();
        for (int o = 128; o > 0; o >>= 1) { if (tid < o) sd[tid] += sd[tid + o]; __syncthreads(); }
        if (tid == 0) {
            float mean = (float)(sd[0] / (4096.0 * 1024.0));
            float mc = fmaxf(mean, 1e-5f);
            g_wscale[a]     = mc;
            g_wscale[2 + a] = 1.0f / mc;
        }
        __syncthreads();
    }
}

// ---------------- fused quantization: w1 | w2 | x -> int8 ----------------
// blocks [0,4096): w1 chunks; [4096,8192): w2 chunks; [8192,16384): x rows
__global__ void __launch_bounds__(256) quant_all(const float* __restrict__ w1,
                                                 const float* __restrict__ w2,
                                                 const float* __restrict__ x) {
    __shared__ float sred[32];
    int blk = blockIdx.x, tid = threadIdx.x;
    if (blk < 8192) {
        int which = (blk >= 4096);
        const float* src = which ? w2 : w1;
        int8_t* dst = which ? g_wq2 : g_wq1;
        size_t idx = (size_t)(blk & 4095) * 1024 + (size_t)tid * 4;
        float sw = g_wscale[2 + which];
        float4 v = *reinterpret_cast<const float4*>(src + idx);
        char4 p;
        p.x = (char)q8(v.x, sw, -1.f, 1.f);
        p.y = (char)q8(v.y, sw, -1.f, 1.f);
        p.z = (char)q8(v.z, sw, -1.f, 1.f);
        p.w = (char)q8(v.w, sw, -1.f, 1.f);
        *reinterpret_cast<char4*>(dst + idx) = p;
    } else {
        int m = blk - 8192;
        float4 v = reinterpret_cast<const float4*>(x + (size_t)m * DM)[tid];
        float amax = fmaxf(fmaxf(fabsf(v.x), fabsf(v.y)), fmaxf(fabsf(v.z), fabsf(v.w)));
        amax = block_max(amax, sred, tid, 256);
        float s = 127.0f / fmaxf(amax, 1e-5f);
        char4 p;
        p.x = (char)q8(v.x, s, -128.f, 127.f);
        p.y = (char)q8(v.y, s, -128.f, 127.f);
        p.z = (char)q8(v.z, s, -128.f, 127.f);
        p.w = (char)q8(v.w, s, -128.f, 127.f);
        *reinterpret_cast<char4*>(g_xq + (size_t)m * DM + (size_t)tid * 4) = p;
        if (tid == 0) g_rowscale1[m] = 1.0f / s;
    }
}

// ---------------- conv3 + SiLU + per-token quant -> int8 ----------------
__global__ void __launch_bounds__(512) conv_silu_quant(const float* __restrict__ cw,
                                                       const float* __restrict__ cb) {
    __shared__ float sred[32];
    int m = blockIdx.x, tid = threadIdx.x;
    int c0 = tid * 8;
    int spos = m & (SS - 1);
    bool has_m = (spos > 0), has_p = (spos < SS - 1);
    const float* h0 = g_h + (size_t)m * DH + c0;

    float hc[8], hm[8], hp[8];
    #pragma unroll
    for (int i = 0; i < 2; i++) {
        float4 v = *reinterpret_cast<const float4*>(h0 + i * 4);
        hc[i*4+0]=v.x; hc[i*4+1]=v.y; hc[i*4+2]=v.z; hc[i*4+3]=v.w;
        float4 vm = has_m ? *reinterpret_cast<const float4*>(h0 - DH + i * 4)
                          : make_float4(0.f,0.f,0.f,0.f);
        hm[i*4+0]=vm.x; hm[i*4+1]=vm.y; hm[i*4+2]=vm.z; hm[i*4+3]=vm.w;
        float4 vp = has_p ? *reinterpret_cast<const float4*>(h0 + DH + i * 4)
                          : make_float4(0.f,0.f,0.f,0.f);
        hp[i*4+0]=vp.x; hp[i*4+1]=vp.y; hp[i*4+2]=vp.z; hp[i*4+3]=vp.w;
    }
    float warr[24];
    #pragma unroll
    for (int i = 0; i < 6; i++) {
        float4 v = *reinterpret_cast<const float4*>(cw + (size_t)c0 * 3 + i * 4);
        warr[i*4+0]=v.x; warr[i*4+1]=v.y; warr[i*4+2]=v.z; warr[i*4+3]=v.w;
    }
    float bv[8];
    #pragma unroll
    for (int i = 0; i < 2; i++) {
        float4 v = *reinterpret_cast<const float4*>(cb + c0 + i * 4);
        bv[i*4+0]=v.x; bv[i*4+1]=v.y; bv[i*4+2]=v.z; bv[i*4+3]=v.w;
    }

    float y[8]; float amax = 0.0f;
    #pragma unroll
    for (int j = 0; j < 8; j++) {
        float t = bv[j];
        t = fmaf(warr[3*j+0], hm[j], t);
        t = fmaf(warr[3*j+1], hc[j], t);
        t = fmaf(warr[3*j+2], hp[j], t);
        t = t / (1.0f + expf(-t));
        y[j] = t;
        amax = fmaxf(amax, fabsf(t));
    }
    amax = block_max(amax, sred, tid, 512);
    float s2 = 127.0f / fmaxf(amax, 1e-5f);

    uint32_t lo = 0, hi = 0;
    #pragma unroll
    for (int j = 0; j < 4; j++) lo |= ((uint32_t)(q8(y[j], s2, -128.f, 127.f) & 0xff)) << (8 * j);
    #pragma unroll
    for (int j = 0; j < 4; j++) hi |= ((uint32_t)(q8(y[4+j], s2, -128.f, 127.f) & 0xff)) << (8 * j);
    *reinterpret_cast<uint2*>(g_q2 + (size_t)m * DH + c0) = make_uint2(lo, hi);
    if (tid == 0) g_rowscale2[m] = 1.0f / s2;
}

// ====== s8 IMMA GEMM: 128x128 block, 256 threads, 2 CTAs/SM, 3-stage cp.async ======
// C[m,n] = (sum_k A[m,k]*B[n,k]) * rowscale[m] * wscale ; A,B K-major int8.
// smem geometry identical to the proven bf16 R7 kernel: 128-byte rows,
// 8x16B chunks, swizzle phys = ch ^ (row&7)  -> conflict-free ldmatrix.
#define BM 128
#define BN 128
#define BKB 128                    // K bytes (=elements) per smem row / stage
#define STAGES 3
#define TILE_BYTES (128 * 128)     // 16 KB per operand tile
#define STAGE_BYTES (2 * TILE_BYTES)
#define GSMEM_TOTAL (STAGES * STAGE_BYTES)   // 96 KB

__device__ __forceinline__ void cp_async16(uint32_t saddr, const void* g) {
    asm volatile("cp.async.cg.shared.global [%0], [%1], 16;\n" :: "r"(saddr), "l"(g));
}
__device__ __forceinline__ void cp_commit() { asm volatile("cp.async.commit_group;\n"); }
__device__ __forceinline__ void cp_wait1()  { asm volatile("cp.async.wait_group 1;\n"); }

__device__ __forceinline__ void ldm_x4(uint32_t* r, uint32_t saddr) {
    asm volatile("ldmatrix.sync.aligned.m8n8.x4.shared.b16 {%0,%1,%2,%3}, [%4];\n"
        : "=r"(r[0]), "=r"(r[1]), "=r"(r[2]), "=r"(r[3]) : "r"(saddr));
}
__device__ __forceinline__ void imma16832(int* d, const uint32_t* a, const uint32_t* b) {
    asm volatile(
        "mma.sync.aligned.m16n8k32.row.col.s32.s8.s8.s32 "
        "{%0,%1,%2,%3},{%4,%5,%6,%7},{%8,%9},{%0,%1,%2,%3};\n"
        : "+r"(d[0]), "+r"(d[1]), "+r"(d[2]), "+r"(d[3])
        : "r"(a[0]), "r"(a[1]), "r"(a[2]), "r"(a[3]), "r"(b[0]), "r"(b[1]));
}

// load one 128x128B A tile + 128x128B B tile with 256 threads (8 cp each)
template <int KK>
__device__ __forceinline__ void load_stage(uint32_t sA, uint32_t sB,
                                           const int8_t* Ag, const int8_t* Bg,
                                           int kByte, int tid) {
    #pragma unroll
    for (int i = 0; i < 4; i++) {          // A: 1024 chunks
        int c = tid + i * 256;
        int row = c >> 3, ch = c & 7;
        int phys = ch ^ (row & 7);
        cp_async16(sA + row * 128 + phys * 16,
                   Ag + (size_t)row * KK + kByte + ch * 16);
    }
    #pragma unroll
    for (int i = 0; i < 4; i++) {          // B: 1024 chunks
        int c = tid + i * 256;
        int row = c >> 3, ch = c & 7;
        int phys = ch ^ (row & 7);
        cp_async16(sB + row * 128 + phys * 16,
                   Bg + (size_t)row * KK + kByte + ch * 16);
    }
    cp_commit();
}

// WHICH=0: A=g_xq B=g_wq1 C=g_h   WHICH=1: A=g_q2 B=g_wq2 C=out
template <int WHICH, int NN, int KK>
__global__ void __launch_bounds__(256, 2) gemm_s8(float* __restrict__ Cout) {
    extern __shared__ __align__(16) char smem[];
    uint32_t s0 = (uint32_t)__cvta_generic_to_shared(smem);

    const int8_t* A  = WHICH ? g_q2 : g_xq;
    const int8_t* B  = WHICH ? g_wq2 : g_wq1;
    float*        C  = WHICH ? Cout : g_h;
    const float*  rs = WHICH ? g_rowscale2 : g_rowscale1;

    const int tid = threadIdx.x, lane = tid & 31, wid = tid >> 5;
    const int wm = (wid >> 1) * 32, wn = (wid & 1) * 64;   // 4x2 warp grid, 32x64 tiles
    const int m0 = blockIdx.y * BM, n0 = blockIdx.x * BN;

    const int8_t* Ag = A + (size_t)m0 * KK;
    const int8_t* Bg = B + (size_t)n0 * KK;

    // ldmatrix per-lane base addressing (same proven pattern as bf16 R7):
    // A x4: lanes 0-15 -> rows (lane&15), k-chunk lo; lanes 16-31 -> same rows, k-chunk hi
    const int rA = wm + (lane & 15);           // + im*16
    const int hiA = lane >> 4;                 // 16B k-chunk select within 32B k-step
    const int xA = rA & 7;
    // B x4: (n-rows 0-7 klo, 0-7 khi, 8-15 klo, 8-15 khi) -> regs (b0,b1) per n-tile
    const int gB = lane >> 3, lrB = lane & 7;
    const int rB = wn + ((gB & 2) << 2) + lrB; // + jp*16
    const int hiB = gB & 1;
    const int xB = rB & 7;

    int acc[2][8][4];
    #pragma unroll
    for (int im = 0; im < 2; im++)
        #pragma unroll
        for (int jn = 0; jn < 8; jn++)
            #pragma unroll
            for (int q = 0; q < 4; q++) acc[im][jn][q] = 0;

    constexpr int KT = KK / BKB;
    #pragma unroll
    for (int p = 0; p < STAGES - 1; p++)
        load_stage<KK>(s0 + p * STAGE_BYTES, s0 + p * STAGE_BYTES + TILE_BYTES,
                       Ag, Bg, p * BKB, tid);

    for (int kt = 0; kt < KT; kt++) {
        cp_wait1();                 // stage kt resident
        __syncthreads();            // all warps done with buffer about to be refilled
        {
            int nk = kt + STAGES - 1;
            if (nk < KT) {
                int pb = nk % STAGES;
                load_stage<KK>(s0 + pb * STAGE_BYTES, s0 + pb * STAGE_BYTES + TILE_BYTES,
                               Ag, Bg, nk * BKB, tid);
            } else {
                cp_commit();        // keep group accounting uniform
            }
        }
        const uint32_t sA = s0 + (uint32_t)(kt % STAGES) * STAGE_BYTES;
        const uint32_t sB = sA + TILE_BYTES;
        const uint32_t aL = sA + (uint32_t)rA * 128;
        const uint32_t bL = sB + (uint32_t)rB * 128;

        #pragma unroll
        for (int ks = 0; ks < 4; ks++) {    // 4 x K=32 per 128B stage
            uint32_t af[2][4], bf[4][4];
            const uint32_t ofA = (uint32_t)(((ks * 2 + hiA) ^ xA) << 4);
            #pragma unroll
            for (int im = 0; im < 2; im++)
                ldm_x4(af[im], aL + (uint32_t)(im * 16 * 128) + ofA);
            const uint32_t ofB = (uint32_t)(((ks * 2 + hiB) ^ xB) << 4);
            #pragma unroll
            for (int jp = 0; jp < 4; jp++)
                ldm_x4(bf[jp], bL + (uint32_t)(jp * 16 * 128) + ofB);
            #pragma unroll
            for (int im = 0; im < 2; im++)
                #pragma unroll
                for (int jn = 0; jn < 8; jn++)
                    imma16832(acc[im][jn], af[im], &bf[jn >> 1][(jn & 1) * 2]);
        }
    }

    const float ws = g_wscale[WHICH];
    const int g = lane >> 2, t = lane & 3;
    #pragma unroll
    for (int im = 0; im < 2; im++) {
        int r0 = m0 + wm + im * 16 + g;
        float rs0 = rs[r0] * ws;
        float rs1 = rs[r0 + 8] * ws;
        #pragma unroll
        for (int jn = 0; jn < 8; jn++) {
            int cc = n0 + wn + jn * 8 + t * 2;
            float2 v0 = make_float2((float)acc[im][jn][0] * rs0, (float)acc[im][jn][1] * rs0);
            float2 v1 = make_float2((float)acc[im][jn][2] * rs1, (float)acc[im][jn][3] * rs1);
            *reinterpret_cast<float2*>(&C[(size_t)r0 * NN + cc]) = v0;
            *reinterpret_cast<float2*>(&C[(size_t)(r0 + 8) * NN + cc]) = v1;
        }
    }
}

// ---------------- launch ----------------
extern "C" void kernel_launch(void* const* d_in, const int* in_sizes, int n_in,
                              void* d_out, int out_size) {
    const float* x  = (const float*)d_in[0];
    const float* w1 = (const float*)d_in[1];
    const float* cw = (const float*)d_in[2];
    const float* cb = (const float*)d_in[3];
    const float* w2 = (const float*)d_in[4];
    float* out = (float*)d_out;
    (void)in_sizes; (void)n_in; (void)out_size;

    static int inited = 0;
    if (!inited) {
        cudaFuncSetAttribute(gemm_s8<0, DH, DM>, cudaFuncAttributeMaxDynamicSharedMemorySize, GSMEM_TOTAL);
        cudaFuncSetAttribute(gemm_s8<1, DM, DH>, cudaFuncAttributeMaxDynamicSharedMemorySize, GSMEM_TOTAL);
        inited = 1;
    }

    wsum_partial<<<8192, 256>>>(w1, w2);                                      // 1
    wsum_final<<<1, 256>>>();                                                 // 2
    quant_all<<<16384, 256>>>(w1, w2, x);                                     // 3
    gemm_s8<0, DH, DM><<<dim3(DH / BN, MM / BM), 256, GSMEM_TOTAL>>>(nullptr);// 4
    conv_silu_quant<<<8192, 512>>>(cw, cb);                                   // 5
    gemm_s8<1, DM, DH><<<dim3(DM / BN, MM / BM), 256, GSMEM_TOTAL>>>(out);    // 6
}

// round 11
// speedup vs baseline: 2.2971x; 2.2971x over previous
#include <cuda_runtime.h>
#include <cuda_bf16.h>
#include <cstdint>
#include <math.h>

#define SS 2048
#define DM 1024
#define DH 4096
#define MM 8192

// ---------------- device scratch ----------------
__device__ double g_partial[8192];
__device__ float  g_wscale[4];
__device__ __align__(16) __nv_bfloat16 g_xq [(size_t)MM * DM];
__device__ __align__(16) __nv_bfloat16 g_wq1[(size_t)DH * DM];
__device__ __align__(16) __nv_bfloat16 g_wq2[(size_t)DM * DH];
__device__ __align__(16) __nv_bfloat16 g_q2 [(size_t)MM * DH];
__device__ __align__(16) float  g_h  [(size_t)MM * DH];
__device__ float g_rowscale1[MM];
__device__ float g_rowscale2[MM];

// ---------------- helpers ----------------
__device__ __forceinline__ uint32_t pack_bf16(float a, float b) {
    __nv_bfloat162 h = __floats2bfloat162_rn(a, b);
    return *reinterpret_cast<uint32_t*>(&h);
}
__device__ __forceinline__ float block_max(float v, float* sred, int tid, int nthr) {
    #pragma unroll
    for (int o = 16; o > 0; o >>= 1) v = fmaxf(v, __shfl_xor_sync(0xFFFFFFFFu, v, o));
    if ((tid & 31) == 0) sred[tid >> 5] = v;
    __syncthreads();
    int nw = nthr >> 5;
    if (tid < 32) {
        float x = (tid < nw) ? sred[tid] : 0.0f;
        #pragma unroll
        for (int o = 16; o > 0; o >>= 1) x = fmaxf(x, __shfl_xor_sync(0xFFFFFFFFu, x, o));
        if (tid == 0) sred[0] = x;
    }
    __syncthreads();
    float r = sred[0];
    __syncthreads();
    return r;
}
__device__ __forceinline__ float qr(float v, float s, float lo, float hi) {
    return fminf(fmaxf(rintf(v * s), lo), hi);
}

// ---------------- weight mean|w| (deterministic) ----------------
__global__ void wsum_partial(const float* __restrict__ w1, const float* __restrict__ w2) {
    __shared__ double sd[256];
    int blk = blockIdx.x;
    const float* src = (blk < 4096) ? (w1 + (size_t)blk * 1024)
                                    : (w2 + (size_t)(blk - 4096) * 1024);
    int tid = threadIdx.x;
    float4 v = reinterpret_cast<const float4*>(src)[tid];
    double s = ((double)fabsf(v.x) + (double)fabsf(v.y)) +
               ((double)fabsf(v.z) + (double)fabsf(v.w));
    sd[tid] = s; __syncthreads();
    for (int o = 128; o > 0; o >>= 1) { if (tid < o) sd[tid] += sd[tid + o]; __syncthreads(); }
    if (tid == 0) g_partial[blk] = sd[0];
}

__global__ void wsum_final() {
    __shared__ double sd[256];
    int tid = threadIdx.x;
    for (int a = 0; a < 2; a++) {
        double s = 0.0;
        for (int i = tid; i < 4096; i += 256) s += g_partial[a * 4096 + i];
        sd[tid] = s; __syncthreads();
        for (int o = 128; o > 0; o >>= 1) { if (tid < o) sd[tid] += sd[tid + o]; __syncthreads(); }
        if (tid == 0) {
            float mean = (float)(sd[0] / (4096.0 * 1024.0));
            float mc = fmaxf(mean, 1e-5f);
            g_wscale[a]     = mc;
            g_wscale[2 + a] = 1.0f / mc;
        }
        __syncthreads();
    }
}

// ---------------- fused quantization: w1 | w2 | x -> bf16 ----------------
__global__ void __launch_bounds__(256) quant_all(const float* __restrict__ w1,
                                                 const float* __restrict__ w2,
                                                 const float* __restrict__ x) {
    __shared__ float sred[32];
    int blk = blockIdx.x, tid = threadIdx.x;
    if (blk < 8192) {
        int which = (blk >= 4096);
        const float* src = which ? w2 : w1;
        __nv_bfloat16* dst = which ? g_wq2 : g_wq1;
        size_t idx = (size_t)(blk & 4095) * 1024 + (size_t)tid * 4;
        float sw = g_wscale[2 + which];
        float4 v = *reinterpret_cast<const float4*>(src + idx);
        uint2 p = make_uint2(pack_bf16(qr(v.x, sw, -1.f, 1.f), qr(v.y, sw, -1.f, 1.f)),
                             pack_bf16(qr(v.z, sw, -1.f, 1.f), qr(v.w, sw, -1.f, 1.f)));
        *reinterpret_cast<uint2*>(dst + idx) = p;
    } else {
        int m = blk - 8192;
        float4 v = reinterpret_cast<const float4*>(x + (size_t)m * DM)[tid];
        float amax = fmaxf(fmaxf(fabsf(v.x), fabsf(v.y)), fmaxf(fabsf(v.z), fabsf(v.w)));
        amax = block_max(amax, sred, tid, 256);
        float s = 127.0f / fmaxf(amax, 1e-5f);
        uint2 p = make_uint2(pack_bf16(qr(v.x, s, -128.f, 127.f), qr(v.y, s, -128.f, 127.f)),
                             pack_bf16(qr(v.z, s, -128.f, 127.f), qr(v.w, s, -128.f, 127.f)));
        *reinterpret_cast<uint2*>(g_xq + (size_t)m * DM + (size_t)tid * 4) = p;
        if (tid == 0) g_rowscale1[m] = 1.0f / s;
    }
}

// ---------------- conv3 + SiLU + per-token quant -> bf16 ----------------
__global__ void __launch_bounds__(512) conv_silu_quant(const float* __restrict__ cw,
                                                       const float* __restrict__ cb) {
    __shared__ float sred[32];
    int m = blockIdx.x, tid = threadIdx.x;
    int c0 = tid * 8;
    int spos = m & (SS - 1);
    bool has_m = (spos > 0), has_p = (spos < SS - 1);
    const float* h0 = g_h + (size_t)m * DH + c0;

    float hc[8], hm[8], hp[8];
    #pragma unroll
    for (int i = 0; i < 2; i++) {
        float4 v = *reinterpret_cast<const float4*>(h0 + i * 4);
        hc[i*4+0]=v.x; hc[i*4+1]=v.y; hc[i*4+2]=v.z; hc[i*4+3]=v.w;
        float4 vm = has_m ? *reinterpret_cast<const float4*>(h0 - DH + i * 4)
                          : make_float4(0.f,0.f,0.f,0.f);
        hm[i*4+0]=vm.x; hm[i*4+1]=vm.y; hm[i*4+2]=vm.z; hm[i*4+3]=vm.w;
        float4 vp = has_p ? *reinterpret_cast<const float4*>(h0 + DH + i * 4)
                          : make_float4(0.f,0.f,0.f,0.f);
        hp[i*4+0]=vp.x; hp[i*4+1]=vp.y; hp[i*4+2]=vp.z; hp[i*4+3]=vp.w;
    }
    float warr[24];
    #pragma unroll
    for (int i = 0; i < 6; i++) {
        float4 v = *reinterpret_cast<const float4*>(cw + (size_t)c0 * 3 + i * 4);
        warr[i*4+0]=v.x; warr[i*4+1]=v.y; warr[i*4+2]=v.z; warr[i*4+3]=v.w;
    }
    float bv[8];
    #pragma unroll
    for (int i = 0; i < 2; i++) {
        float4 v = *reinterpret_cast<const float4*>(cb + c0 + i * 4);
        bv[i*4+0]=v.x; bv[i*4+1]=v.y; bv[i*4+2]=v.z; bv[i*4+3]=v.w;
    }

    float y[8]; float amax = 0.0f;
    #pragma unroll
    for (int j = 0; j < 8; j++) {
        float t = bv[j];
        t = fmaf(warr[3*j+0], hm[j], t);
        t = fmaf(warr[3*j+1], hc[j], t);
        t = fmaf(warr[3*j+2], hp[j], t);
        t = t / (1.0f + expf(-t));
        y[j] = t;
        amax = fmaxf(amax, fabsf(t));
    }
    amax = block_max(amax, sred, tid, 512);
    float s2 = 127.0f / fmaxf(amax, 1e-5f);

    uint4 p;
    p.x = pack_bf16(qr(y[0], s2, -128.f, 127.f), qr(y[1], s2, -128.f, 127.f));
    p.y = pack_bf16(qr(y[2], s2, -128.f, 127.f), qr(y[3], s2, -128.f, 127.f));
    p.z = pack_bf16(qr(y[4], s2, -128.f, 127.f), qr(y[5], s2, -128.f, 127.f));
    p.w = pack_bf16(qr(y[6], s2, -128.f, 127.f), qr(y[7], s2, -128.f, 127.f));
    *reinterpret_cast<uint4*>(g_q2 + (size_t)m * DH + c0) = p;
    if (tid == 0) g_rowscale2[m] = 1.0f / s2;
}

// ====== bf16 HMMA GEMM: 128x128 block, 128 threads, 64x64 warp tiles ======
// 2 CTAs/SM, 3-stage cp.async, ks-level fragment double-buffering.
// C[m,n] = (sum_k A[m,k]*B[n,k]) * rowscale[m] * wscale ; A,B K-major bf16.
#define BM 128
#define BN 128
#define BK 64                      // 64 bf16 = 128 bytes per smem row
#define STAGES 3
#define TILE_BYTES (128 * 128)     // 16 KB per operand tile
#define STAGE_BYTES (2 * TILE_BYTES)
#define GSMEM_TOTAL (STAGES * STAGE_BYTES)   // 96 KB

__device__ __forceinline__ void cp_async16(uint32_t saddr, const void* g) {
    asm volatile("cp.async.cg.shared.global [%0], [%1], 16;\n" :: "r"(saddr), "l"(g));
}
__device__ __forceinline__ void cp_commit() { asm volatile("cp.async.commit_group;\n"); }
__device__ __forceinline__ void cp_wait1()  { asm volatile("cp.async.wait_group 1;\n"); }

__device__ __forceinline__ void ldm_x4(uint32_t* r, uint32_t saddr) {
    asm volatile("ldmatrix.sync.aligned.m8n8.x4.shared.b16 {%0,%1,%2,%3}, [%4];\n"
        : "=r"(r[0]), "=r"(r[1]), "=r"(r[2]), "=r"(r[3]) : "r"(saddr));
}
__device__ __forceinline__ void mma16816(float* d, const uint32_t* a, const uint32_t* b) {
    asm volatile(
        "mma.sync.aligned.m16n8k16.row.col.f32.bf16.bf16.f32 "
        "{%0,%1,%2,%3},{%4,%5,%6,%7},{%8,%9},{%0,%1,%2,%3};\n"
        : "+f"(d[0]), "+f"(d[1]), "+f"(d[2]), "+f"(d[3])
        : "r"(a[0]), "r"(a[1]), "r"(a[2]), "r"(a[3]), "r"(b[0]), "r"(b[1]));
}

// load one 128x64 A tile + 128x64 B tile with 128 threads (16 cp each)
// 16B-chunk swizzle: phys = ch ^ (row&7)  -> conflict-free ldmatrix + stores
template <int KK>
__device__ __forceinline__ void load_stage(uint32_t sA, uint32_t sB,
                                           const __nv_bfloat16* Ag, const __nv_bfloat16* Bg,
                                           int kElem, int tid) {
    #pragma unroll
    for (int i = 0; i < 8; i++) {          // A: 1024 chunks
        int c = tid + i * 128;
        int row = c >> 3, ch = c & 7;
        int phys = ch ^ (row & 7);
        cp_async16(sA + row * 128 + phys * 16,
                   (const char*)(Ag + (size_t)row * KK + kElem) + ch * 16);
    }
    #pragma unroll
    for (int i = 0; i < 8; i++) {          // B: 1024 chunks
        int c = tid + i * 128;
        int row = c >> 3, ch = c & 7;
        int phys = ch ^ (row & 7);
        cp_async16(sB + row * 128 + phys * 16,
                   (const char*)(Bg + (size_t)row * KK + kElem) + ch * 16);
    }
    cp_commit();
}

// WHICH=0: A=g_xq B=g_wq1 C=g_h   WHICH=1: A=g_q2 B=g_wq2 C=out
template <int WHICH, int NN, int KK>
__global__ void __launch_bounds__(128, 2) gemm_bf16(float* __restrict__ Cout) {
    extern __shared__ __align__(16) char smem[];
    uint32_t s0 = (uint32_t)__cvta_generic_to_shared(smem);

    const __nv_bfloat16* A  = WHICH ? g_q2 : g_xq;
    const __nv_bfloat16* B  = WHICH ? g_wq2 : g_wq1;
    float*               C  = WHICH ? Cout : g_h;
    const float*         rs = WHICH ? g_rowscale2 : g_rowscale1;

    const int tid = threadIdx.x, lane = tid & 31, wid = tid >> 5;
    const int wm = (wid >> 1) * 64, wn = (wid & 1) * 64;   // 2x2 warp grid, 64x64 tiles
    const int m0 = blockIdx.y * BM, n0 = blockIdx.x * BN;

    const __nv_bfloat16* Ag = A + (size_t)m0 * KK;
    const __nv_bfloat16* Bg = B + (size_t)n0 * KK;

    // ldmatrix per-lane base addressing (proven R7 pattern)
    const int rA = wm + (lane & 15);           // + im*16
    const int hiA = lane >> 4;                 // k-half select
    const int xA = rA & 7;
    const int gB = lane >> 3, lrB = lane & 7;
    const int rB = wn + ((gB & 2) << 2) + lrB; // + jp*16
    const int hiB = gB & 1;
    const int xB = rB & 7;

    float acc[4][8][4];
    #pragma unroll
    for (int im = 0; im < 4; im++)
        #pragma unroll
        for (int jn = 0; jn < 8; jn++)
            #pragma unroll
            for (int q = 0; q < 4; q++) acc[im][jn][q] = 0.0f;

    uint32_t af[2][4][4], bf[2][4][4];   // double-buffered fragments

    constexpr int KT = KK / BK;
    #pragma unroll
    for (int p = 0; p < STAGES - 1; p++)
        load_stage<KK>(s0 + p * STAGE_BYTES, s0 + p * STAGE_BYTES + TILE_BYTES,
                       Ag, Bg, p * BK, tid);

    for (int kt = 0; kt < KT; kt++) {
        cp_wait1();                 // stage kt resident
        __syncthreads();            // all warps done with buffer about to be refilled

        const uint32_t sA = s0 + (uint32_t)(kt % STAGES) * STAGE_BYTES;
        const uint32_t sB = sA + TILE_BYTES;
        const uint32_t aL = sA + (uint32_t)rA * 128;
        const uint32_t bL = sB + (uint32_t)rB * 128;

        // ks=0 fragments first (gets LDSM started before the cp.async burst)
        {
            const uint32_t ofA = (uint32_t)((hiA ^ xA) << 4);
            #pragma unroll
            for (int im = 0; im < 4; im++)
                ldm_x4(af[0][im], aL + (uint32_t)(im * 16 * 128) + ofA);
            const uint32_t ofB = (uint32_t)((hiB ^ xB) << 4);
            #pragma unroll
            for (int jp = 0; jp < 4; jp++)
                ldm_x4(bf[0][jp], bL + (uint32_t)(jp * 16 * 128) + ofB);
        }

        // prefetch stage kt+2
        {
            int nk = kt + STAGES - 1;
            if (nk < KT) {
                int pb = nk % STAGES;
                load_stage<KK>(s0 + pb * STAGE_BYTES, s0 + pb * STAGE_BYTES + TILE_BYTES,
                               Ag, Bg, nk * BK, tid);
            } else {
                cp_commit();        // keep group accounting uniform
            }
        }

        #pragma unroll
        for (int ks = 0; ks < 4; ks++) {
            const int cur = ks & 1;
            if (ks < 3) {           // prefetch next k-chunk fragments
                const int nxt = cur ^ 1;
                const uint32_t ofA = (uint32_t)((((ks + 1) * 2 + hiA) ^ xA) << 4);
                #pragma unroll
                for (int im = 0; im < 4; im++)
                    ldm_x4(af[nxt][im], aL + (uint32_t)(im * 16 * 128) + ofA);
                const uint32_t ofB = (uint32_t)((((ks + 1) * 2 + hiB) ^ xB) << 4);
                #pragma unroll
                for (int jp = 0; jp < 4; jp++)
                    ldm_x4(bf[nxt][jp], bL + (uint32_t)(jp * 16 * 128) + ofB);
            }
            #pragma unroll
            for (int im = 0; im < 4; im++)
                #pragma unroll
                for (int jn = 0; jn < 8; jn++)
                    mma16816(acc[im][jn], af[cur][im], &bf[cur][jn >> 1][(jn & 1) * 2]);
        }
    }

    const float ws = g_wscale[WHICH];
    const int g = lane >> 2, t = lane & 3;
    #pragma unroll
    for (int im = 0; im < 4; im++) {
        int r0 = m0 + wm + im * 16 + g;
        float rs0 = rs[r0] * ws;
        float rs1 = rs[r0 + 8] * ws;
        #pragma unroll
        for (int jn = 0; jn < 8; jn++) {
            int cc = n0 + wn + jn * 8 + t * 2;
            float2 v0 = make_float2(acc[im][jn][0] * rs0, acc[im][jn][1] * rs0);
            float2 v1 = make_float2(acc[im][jn][2] * rs1, acc[im][jn][3] * rs1);
            *reinterpret_cast<float2*>(&C[(size_t)r0 * NN + cc]) = v0;
            *reinterpret_cast<float2*>(&C[(size_t)(r0 + 8) * NN + cc]) = v1;
        }
    }
}

// ---------------- launch ----------------
extern "C" void kernel_launch(void* const* d_in, const int* in_sizes, int n_in,
                              void* d_out, int out_size) {
    const float* x  = (const float*)d_in[0];
    const float* w1 = (const float*)d_in[1];
    const float* cw = (const float*)d_in[2];
    const float* cb = (const float*)d_in[3];
    const float* w2 = (const float*)d_in[4];
    float* out = (float*)d_out;
    (void)in_sizes; (void)n_in; (void)out_size;

    static int inited = 0;
    if (!inited) {
        cudaFuncSetAttribute(gemm_bf16<0, DH, DM>, cudaFuncAttributeMaxDynamicSharedMemorySize, GSMEM_TOTAL);
        cudaFuncSetAttribute(gemm_bf16<1, DM, DH>, cudaFuncAttributeMaxDynamicSharedMemorySize, GSMEM_TOTAL);
        inited = 1;
    }

    wsum_partial<<<8192, 256>>>(w1, w2);                                        // 1
    wsum_final<<<1, 256>>>();                                                   // 2
    quant_all<<<16384, 256>>>(w1, w2, x);                                       // 3
    gemm_bf16<0, DH, DM><<<dim3(DH / BN, MM / BM), 128, GSMEM_TOTAL>>>(nullptr);// 4
    conv_silu_quant<<<8192, 512>>>(cw, cb);                                     // 5
    gemm_bf16<1, DM, DH><<<dim3(DM / BN, MM / BM), 128, GSMEM_TOTAL>>>(out);    // 6
}

// round 12
// speedup vs baseline: 2.4733x; 1.0767x over previous
#include <cuda_runtime.h>
#include <cuda_bf16.h>
#include <cstdint>
#include <math.h>

#define SS 2048
#define DM 1024
#define DH 4096
#define MM 8192

// ---------------- device scratch ----------------
__device__ double g_partial[8192];
__device__ float  g_wscale[4];
__device__ __align__(16) __nv_bfloat16 g_xq [(size_t)MM * DM];
__device__ __align__(16) __nv_bfloat16 g_wq1[(size_t)DH * DM];
__device__ __align__(16) __nv_bfloat16 g_wq2[(size_t)DM * DH];
__device__ __align__(16) __nv_bfloat16 g_q2 [(size_t)MM * DH];
__device__ __align__(16) float  g_h  [(size_t)MM * DH];
__device__ float g_rowscale1[MM];
__device__ float g_rowscale2[MM];

// ---------------- helpers ----------------
__device__ __forceinline__ uint32_t pack_bf16(float a, float b) {
    __nv_bfloat162 h = __floats2bfloat162_rn(a, b);
    return *reinterpret_cast<uint32_t*>(&h);
}
__device__ __forceinline__ float block_max(float v, float* sred, int tid, int nthr) {
    #pragma unroll
    for (int o = 16; o > 0; o >>= 1) v = fmaxf(v, __shfl_xor_sync(0xFFFFFFFFu, v, o));
    if ((tid & 31) == 0) sred[tid >> 5] = v;
    __syncthreads();
    int nw = nthr >> 5;
    if (tid < 32) {
        float x = (tid < nw) ? sred[tid] : 0.0f;
        #pragma unroll
        for (int o = 16; o > 0; o >>= 1) x = fmaxf(x, __shfl_xor_sync(0xFFFFFFFFu, x, o));
        if (tid == 0) sred[0] = x;
    }
    __syncthreads();
    float r = sred[0];
    __syncthreads();
    return r;
}
__device__ __forceinline__ float qr(float v, float s, float lo, float hi) {
    return fminf(fmaxf(rintf(v * s), lo), hi);
}

// ---------------- weight mean|w| (deterministic) ----------------
__global__ void wsum_partial(const float* __restrict__ w1, const float* __restrict__ w2) {
    __shared__ double sd[256];
    int blk = blockIdx.x;
    const float* src = (blk < 4096) ? (w1 + (size_t)blk * 1024)
                                    : (w2 + (size_t)(blk - 4096) * 1024);
    int tid = threadIdx.x;
    float4 v = reinterpret_cast<const float4*>(src)[tid];
    double s = ((double)fabsf(v.x) + (double)fabsf(v.y)) +
               ((double)fabsf(v.z) + (double)fabsf(v.w));
    sd[tid] = s; __syncthreads();
    for (int o = 128; o > 0; o >>= 1) { if (tid < o) sd[tid] += sd[tid + o]; __syncthreads(); }
    if (tid == 0) g_partial[blk] = sd[0];
}

__global__ void wsum_final() {
    __shared__ double sd[256];
    int tid = threadIdx.x;
    for (int a = 0; a < 2; a++) {
        double s = 0.0;
        for (int i = tid; i < 4096; i += 256) s += g_partial[a * 4096 + i];
        sd[tid] = s; __syncthreads();
        for (int o = 128; o > 0; o >>= 1) { if (tid < o) sd[tid] += sd[tid + o]; __syncthreads(); }
        if (tid == 0) {
            float mean = (float)(sd[0] / (4096.0 * 1024.0));
            float mc = fmaxf(mean, 1e-5f);
            g_wscale[a]     = mc;
            g_wscale[2 + a] = 1.0f / mc;
        }
        __syncthreads();
    }
}

// ---------------- fused quantization: w1 | w2 | x -> bf16 ----------------
__global__ void __launch_bounds__(256) quant_all(const float* __restrict__ w1,
                                                 const float* __restrict__ w2,
                                                 const float* __restrict__ x) {
    __shared__ float sred[32];
    int blk = blockIdx.x, tid = threadIdx.x;
    if (blk < 8192) {
        int which = (blk >= 4096);
        const float* src = which ? w2 : w1;
        __nv_bfloat16* dst = which ? g_wq2 : g_wq1;
        size_t idx = (size_t)(blk & 4095) * 1024 + (size_t)tid * 4;
        float sw = g_wscale[2 + which];
        float4 v = *reinterpret_cast<const float4*>(src + idx);
        uint2 p = make_uint2(pack_bf16(qr(v.x, sw, -1.f, 1.f), qr(v.y, sw, -1.f, 1.f)),
                             pack_bf16(qr(v.z, sw, -1.f, 1.f), qr(v.w, sw, -1.f, 1.f)));
        *reinterpret_cast<uint2*>(dst + idx) = p;
    } else {
        int m = blk - 8192;
        float4 v = reinterpret_cast<const float4*>(x + (size_t)m * DM)[tid];
        float amax = fmaxf(fmaxf(fabsf(v.x), fabsf(v.y)), fmaxf(fabsf(v.z), fabsf(v.w)));
        amax = block_max(amax, sred, tid, 256);
        float s = 127.0f / fmaxf(amax, 1e-5f);
        uint2 p = make_uint2(pack_bf16(qr(v.x, s, -128.f, 127.f), qr(v.y, s, -128.f, 127.f)),
                             pack_bf16(qr(v.z, s, -128.f, 127.f), qr(v.w, s, -128.f, 127.f)));
        *reinterpret_cast<uint2*>(g_xq + (size_t)m * DM + (size_t)tid * 4) = p;
        if (tid == 0) g_rowscale1[m] = 1.0f / s;
    }
}

// ---------------- conv3 + SiLU + per-token quant, 4 tokens/block ----------------
// grid = MM/4 blocks of 512 threads; thread owns 8 channels, slides a 3-row
// window over rows g0-1 .. g0+4. Reads 6 rows per 4 tokens (1.5x vs 3x).
__global__ void __launch_bounds__(512) conv_silu_quant4(const float* __restrict__ cw,
                                                        const float* __restrict__ cb) {
    __shared__ float sred4[16][4];
    __shared__ float s2s[4];
    int g0 = blockIdx.x * 4;              // first token of group (never crosses batch)
    int tid = threadIdx.x;
    int c0 = tid * 8;
    int spos0 = g0 & (SS - 1);

    // conv weights / bias for these 8 channels
    float warr[24];
    #pragma unroll
    for (int i = 0; i < 6; i++) {
        float4 v = *reinterpret_cast<const float4*>(cw + (size_t)c0 * 3 + i * 4);
        warr[i*4+0]=v.x; warr[i*4+1]=v.y; warr[i*4+2]=v.z; warr[i*4+3]=v.w;
    }
    float bv[8];
    #pragma unroll
    for (int i = 0; i < 2; i++) {
        float4 v = *reinterpret_cast<const float4*>(cb + c0 + i * 4);
        bv[i*4+0]=v.x; bv[i*4+1]=v.y; bv[i*4+2]=v.z; bv[i*4+3]=v.w;
    }

    const float* hbase = g_h + (size_t)g0 * DH + c0;

    // 3-row sliding window
    float w0r[8], w1r[8], w2r[8];
    // row r corresponds to token g0-1+r ; valid iff 0 <= spos0+r-1 <= SS-1
    // r=0 invalid iff spos0==0 ; r=5 invalid iff spos0==SS-4
    #pragma unroll
    for (int i = 0; i < 2; i++) {
        float4 vm = (spos0 > 0) ? *reinterpret_cast<const float4*>(hbase - DH + i * 4)
                                : make_float4(0.f,0.f,0.f,0.f);
        w0r[i*4+0]=vm.x; w0r[i*4+1]=vm.y; w0r[i*4+2]=vm.z; w0r[i*4+3]=vm.w;
        float4 vc = *reinterpret_cast<const float4*>(hbase + i * 4);
        w1r[i*4+0]=vc.x; w1r[i*4+1]=vc.y; w1r[i*4+2]=vc.z; w1r[i*4+3]=vc.w;
    }

    float y[4][8];
    float amax[4];
    #pragma unroll
    for (int t = 0; t < 4; t++) {
        // load row t+2 (token g0+t+1): valid unless t==3 && spos0==SS-4
        bool valid = !(t == 3 && spos0 == SS - 4);
        #pragma unroll
        for (int i = 0; i < 2; i++) {
            float4 vp = valid ? *reinterpret_cast<const float4*>(hbase + (size_t)(t + 1) * DH + i * 4)
                              : make_float4(0.f,0.f,0.f,0.f);
            w2r[i*4+0]=vp.x; w2r[i*4+1]=vp.y; w2r[i*4+2]=vp.z; w2r[i*4+3]=vp.w;
        }
        float am = 0.0f;
        #pragma unroll
        for (int j = 0; j < 8; j++) {
            float v = bv[j];
            v = fmaf(warr[3*j+0], w0r[j], v);
            v = fmaf(warr[3*j+1], w1r[j], v);
            v = fmaf(warr[3*j+2], w2r[j], v);
            v = v / (1.0f + expf(-v));        // SiLU
            y[t][j] = v;
            am = fmaxf(am, fabsf(v));
        }
        amax[t] = am;
        // slide window
        #pragma unroll
        for (int j = 0; j < 8; j++) { w0r[j] = w1r[j]; w1r[j] = w2r[j]; }
    }

    // fused 4-way block max
    #pragma unroll
    for (int t = 0; t < 4; t++) {
        float v = amax[t];
        #pragma unroll
        for (int o = 16; o > 0; o >>= 1) v = fmaxf(v, __shfl_xor_sync(0xFFFFFFFFu, v, o));
        if ((tid & 31) == 0) sred4[tid >> 5][t] = v;
    }
    __syncthreads();
    if (tid < 128) {                     // warps 0..3 finalize t = wid
        int w = tid >> 5, lane = tid & 31;
        float v = (lane < 16) ? sred4[lane][w] : 0.0f;
        #pragma unroll
        for (int o = 8; o > 0; o >>= 1) v = fmaxf(v, __shfl_xor_sync(0xFFFFFFFFu, v, o));
        if (lane == 0) {
            float s2 = 127.0f / fmaxf(v, 1e-5f);
            s2s[w] = s2;
            g_rowscale2[g0 + w] = 1.0f / s2;
        }
    }
    __syncthreads();

    #pragma unroll
    for (int t = 0; t < 4; t++) {
        float s2 = s2s[t];
        uint4 p;
        p.x = pack_bf16(qr(y[t][0], s2, -128.f, 127.f), qr(y[t][1], s2, -128.f, 127.f));
        p.y = pack_bf16(qr(y[t][2], s2, -128.f, 127.f), qr(y[t][3], s2, -128.f, 127.f));
        p.z = pack_bf16(qr(y[t][4], s2, -128.f, 127.f), qr(y[t][5], s2, -128.f, 127.f));
        p.w = pack_bf16(qr(y[t][6], s2, -128.f, 127.f), qr(y[t][7], s2, -128.f, 127.f));
        *reinterpret_cast<uint4*>(g_q2 + (size_t)(g0 + t) * DH + c0) = p;
    }
}

// ====== bf16 HMMA GEMM: 128x128 block, 128 threads, 64x64 warp tiles ======
// 2 CTAs/SM, 3-stage cp.async, ks-level fragment double-buffering.
// C[m,n] = (sum_k A[m,k]*B[n,k]) * rowscale[m] * wscale ; A,B K-major bf16.
#define BM 128
#define BN 128
#define BK 64                      // 64 bf16 = 128 bytes per smem row
#define STAGES 3
#define TILE_BYTES (128 * 128)     // 16 KB per operand tile
#define STAGE_BYTES (2 * TILE_BYTES)
#define GSMEM_TOTAL (STAGES * STAGE_BYTES)   // 96 KB

__device__ __forceinline__ void cp_async16(uint32_t saddr, const void* g) {
    asm volatile("cp.async.cg.shared.global [%0], [%1], 16;\n" :: "r"(saddr), "l"(g));
}
__device__ __forceinline__ void cp_commit() { asm volatile("cp.async.commit_group;\n"); }
__device__ __forceinline__ void cp_wait1()  { asm volatile("cp.async.wait_group 1;\n"); }

__device__ __forceinline__ void ldm_x4(uint32_t* r, uint32_t saddr) {
    asm volatile("ldmatrix.sync.aligned.m8n8.x4.shared.b16 {%0,%1,%2,%3}, [%4];\n"
        : "=r"(r[0]), "=r"(r[1]), "=r"(r[2]), "=r"(r[3]) : "r"(saddr));
}
__device__ __forceinline__ void mma16816(float* d, const uint32_t* a, const uint32_t* b) {
    asm volatile(
        "mma.sync.aligned.m16n8k16.row.col.f32.bf16.bf16.f32 "
        "{%0,%1,%2,%3},{%4,%5,%6,%7},{%8,%9},{%0,%1,%2,%3};\n"
        : "+f"(d[0]), "+f"(d[1]), "+f"(d[2]), "+f"(d[3])
        : "r"(a[0]), "r"(a[1]), "r"(a[2]), "r"(a[3]), "r"(b[0]), "r"(b[1]));
}

// load one 128x64 A tile + 128x64 B tile with 128 threads (16 cp each)
// 16B-chunk swizzle: phys = ch ^ (row&7)  -> conflict-free ldmatrix + stores
template <int KK>
__device__ __forceinline__ void load_stage(uint32_t sA, uint32_t sB,
                                           const __nv_bfloat16* Ag, const __nv_bfloat16* Bg,
                                           int kElem, int tid) {
    #pragma unroll
    for (int i = 0; i < 8; i++) {          // A: 1024 chunks
        int c = tid + i * 128;
        int row = c >> 3, ch = c & 7;
        int phys = ch ^ (row & 7);
        cp_async16(sA + row * 128 + phys * 16,
                   (const char*)(Ag + (size_t)row * KK + kElem) + ch * 16);
    }
    #pragma unroll
    for (int i = 0; i < 8; i++) {          // B: 1024 chunks
        int c = tid + i * 128;
        int row = c >> 3, ch = c & 7;
        int phys = ch ^ (row & 7);
        cp_async16(sB + row * 128 + phys * 16,
                   (const char*)(Bg + (size_t)row * KK + kElem) + ch * 16);
    }
    cp_commit();
}

// WHICH=0: A=g_xq B=g_wq1 C=g_h   WHICH=1: A=g_q2 B=g_wq2 C=out
template <int WHICH, int NN, int KK>
__global__ void __launch_bounds__(128, 2) gemm_bf16(float* __restrict__ Cout) {
    extern __shared__ __align__(16) char smem[];
    uint32_t s0 = (uint32_t)__cvta_generic_to_shared(smem);

    const __nv_bfloat16* A  = WHICH ? g_q2 : g_xq;
    const __nv_bfloat16* B  = WHICH ? g_wq2 : g_wq1;
    float*               C  = WHICH ? Cout : g_h;
    const float*         rs = WHICH ? g_rowscale2 : g_rowscale1;

    const int tid = threadIdx.x, lane = tid & 31, wid = tid >> 5;
    const int wm = (wid >> 1) * 64, wn = (wid & 1) * 64;   // 2x2 warp grid, 64x64 tiles
    const int m0 = blockIdx.y * BM, n0 = blockIdx.x * BN;

    const __nv_bfloat16* Ag = A + (size_t)m0 * KK;
    const __nv_bfloat16* Bg = B + (size_t)n0 * KK;

    // ldmatrix per-lane base addressing (proven R7 pattern)
    const int rA = wm + (lane & 15);           // + im*16
    const int hiA = lane >> 4;                 // k-half select
    const int xA = rA & 7;
    const int gB = lane >> 3, lrB = lane & 7;
    const int rB = wn + ((gB & 2) << 2) + lrB; // + jp*16
    const int hiB = gB & 1;
    const int xB = rB & 7;

    float acc[4][8][4];
    #pragma unroll
    for (int im = 0; im < 4; im++)
        #pragma unroll
        for (int jn = 0; jn < 8; jn++)
            #pragma unroll
            for (int q = 0; q < 4; q++) acc[im][jn][q] = 0.0f;

    uint32_t af[2][4][4], bf[2][4][4];   // double-buffered fragments

    constexpr int KT = KK / BK;
    #pragma unroll
    for (int p = 0; p < STAGES - 1; p++)
        load_stage<KK>(s0 + p * STAGE_BYTES, s0 + p * STAGE_BYTES + TILE_BYTES,
                       Ag, Bg, p * BK, tid);

    for (int kt = 0; kt < KT; kt++) {
        cp_wait1();                 // stage kt resident
        __syncthreads();            // all warps done with buffer about to be refilled

        const uint32_t sA = s0 + (uint32_t)(kt % STAGES) * STAGE_BYTES;
        const uint32_t sB = sA + TILE_BYTES;
        const uint32_t aL = sA + (uint32_t)rA * 128;
        const uint32_t bL = sB + (uint32_t)rB * 128;

        // ks=0 fragments first (gets LDSM started before the cp.async burst)
        {
            const uint32_t ofA = (uint32_t)((hiA ^ xA) << 4);
            #pragma unroll
            for (int im = 0; im < 4; im++)
                ldm_x4(af[0][im], aL + (uint32_t)(im * 16 * 128) + ofA);
            const uint32_t ofB = (uint32_t)((hiB ^ xB) << 4);
            #pragma unroll
            for (int jp = 0; jp < 4; jp++)
                ldm_x4(bf[0][jp], bL + (uint32_t)(jp * 16 * 128) + ofB);
        }

        // prefetch stage kt+2
        {
            int nk = kt + STAGES - 1;
            if (nk < KT) {
                int pb = nk % STAGES;
                load_stage<KK>(s0 + pb * STAGE_BYTES, s0 + pb * STAGE_BYTES + TILE_BYTES,
                               Ag, Bg, nk * BK, tid);
            } else {
                cp_commit();        // keep group accounting uniform
            }
        }

        #pragma unroll
        for (int ks = 0; ks < 4; ks++) {
            const int cur = ks & 1;
            if (ks < 3) {           // prefetch next k-chunk fragments
                const int nxt = cur ^ 1;
                const uint32_t ofA = (uint32_t)((((ks + 1) * 2 + hiA) ^ xA) << 4);
                #pragma unroll
                for (int im = 0; im < 4; im++)
                    ldm_x4(af[nxt][im], aL + (uint32_t)(im * 16 * 128) + ofA);
                const uint32_t ofB = (uint32_t)((((ks + 1) * 2 + hiB) ^ xB) << 4);
                #pragma unroll
                for (int jp = 0; jp < 4; jp++)
                    ldm_x4(bf[nxt][jp], bL + (uint32_t)(jp * 16 * 128) + ofB);
            }
            #pragma unroll
            for (int im = 0; im < 4; im++)
                #pragma unroll
                for (int jn = 0; jn < 8; jn++)
                    mma16816(acc[im][jn], af[cur][im], &bf[cur][jn >> 1][(jn & 1) * 2]);
        }
    }

    const float ws = g_wscale[WHICH];
    const int g = lane >> 2, t = lane & 3;
    #pragma unroll
    for (int im = 0; im < 4; im++) {
        int r0 = m0 + wm + im * 16 + g;
        float rs0 = rs[r0] * ws;
        float rs1 = rs[r0 + 8] * ws;
        #pragma unroll
        for (int jn = 0; jn < 8; jn++) {
            int cc = n0 + wn + jn * 8 + t * 2;
            float2 v0 = make_float2(acc[im][jn][0] * rs0, acc[im][jn][1] * rs0);
            float2 v1 = make_float2(acc[im][jn][2] * rs1, acc[im][jn][3] * rs1);
            *reinterpret_cast<float2*>(&C[(size_t)r0 * NN + cc]) = v0;
            *reinterpret_cast<float2*>(&C[(size_t)(r0 + 8) * NN + cc]) = v1;
        }
    }
}

// ---------------- launch ----------------
extern "C" void kernel_launch(void* const* d_in, const int* in_sizes, int n_in,
                              void* d_out, int out_size) {
    const float* x  = (const float*)d_in[0];
    const float* w1 = (const float*)d_in[1];
    const float* cw = (const float*)d_in[2];
    const float* cb = (const float*)d_in[3];
    const float* w2 = (const float*)d_in[4];
    float* out = (float*)d_out;
    (void)in_sizes; (void)n_in; (void)out_size;

    static int inited = 0;
    if (!inited) {
        cudaFuncSetAttribute(gemm_bf16<0, DH, DM>, cudaFuncAttributeMaxDynamicSharedMemorySize, GSMEM_TOTAL);
        cudaFuncSetAttribute(gemm_bf16<1, DM, DH>, cudaFuncAttributeMaxDynamicSharedMemorySize, GSMEM_TOTAL);
        inited = 1;
    }

    wsum_partial<<<8192, 256>>>(w1, w2);                                        // 1
    wsum_final<<<1, 256>>>();                                                   // 2
    quant_all<<<16384, 256>>>(w1, w2, x);                                       // 3
    gemm_bf16<0, DH, DM><<<dim3(DH / BN, MM / BM), 128, GSMEM_TOTAL>>>(nullptr);// 4
    conv_silu_quant4<<<MM / 4, 512>>>(cw, cb);                                  // 5
    gemm_bf16<1, DM, DH><<<dim3(DM / BN, MM / BM), 128, GSMEM_TOTAL>>>(out);    // 6
}